// round 4
// baseline (speedup 1.0000x reference)
#include <cuda_runtime.h>
#include <cstdint>

// ---------------- problem constants ----------------
#define E_   16
#define B_   4096
#define DX_  128
#define DC_  64
#define DIN_ 192
#define DH_  1024
#define DO_  128

#define BM   128            // batch rows per CTA
#define CHN  32             // DH chunk
#define NCH  (DH_/CHN)      // 32 chunks
#define THREADS 256

// smem row strides (floats):
//  A-operand sources (64-bit pair loads): stride % 32 == 8
//  B-operand sources (32-bit loads):      stride % 32 == 4
#define SXC 200   // xc  [128][200]  permuted tf32
#define SW1 196   // W1  [32][196]   plain k-major tf32, double buffered
#define SW2 36    // W2  [128][36]   plain k-major tf32, double buffered
#define SH  40    // h   [128][40]   permuted tf32

// smem offsets in floats
#define OFF_XC 0
#define N_XC   (BM*SXC)                 // 25600
#define OFF_W1 (OFF_XC + N_XC)          // 25600
#define N_W1   (CHN*SW1)                // 6272 per buf
#define OFF_W2 (OFF_W1 + 2*N_W1)        // 38144
#define N_W2   (DO_*SW2)                // 4608 per buf
#define OFF_H  (OFF_W2 + 2*N_W2)        // 47360
#define N_H    (BM*SH)                  // 5120
#define OFF_B1 (OFF_H + N_H)            // 52480
#define OFF_B2 (OFF_B1 + DH_)           // 53504
#define SMEM_FLOATS (OFF_B2 + DO_)      // 53632
#define SMEM_BYTES  (SMEM_FLOATS*4)     // 214528

// ---------------- helpers ----------------
__device__ __forceinline__ uint32_t f2tf32(float f){
    uint32_t u; asm("cvt.rna.tf32.f32 %0, %1;" : "=r"(u) : "f"(f)); return u;
}
__device__ __forceinline__ float tf32relu(float v){
    float r = fmaxf(v, 0.0f);
    uint32_t u; asm("cvt.rna.tf32.f32 %0, %1;" : "=r"(u) : "f"(r));
    return __uint_as_float(u);
}
// store one k-group of 8 (lo=k0..3, hi=k4..7) as pairs [0,4][1,5][2,6][3,7], tf32-converted
__device__ __forceinline__ void put_group(float4 lo, float4 hi, float* dst){
    uint2 p;
    p.x = f2tf32(lo.x); p.y = f2tf32(hi.x); *(uint2*)(dst + 0) = p;
    p.x = f2tf32(lo.y); p.y = f2tf32(hi.y); *(uint2*)(dst + 2) = p;
    p.x = f2tf32(lo.z); p.y = f2tf32(hi.z); *(uint2*)(dst + 4) = p;
    p.x = f2tf32(lo.w); p.y = f2tf32(hi.w); *(uint2*)(dst + 6) = p;
}
__device__ __forceinline__ uint4 cvt4(uint4 r){
    uint4 c;
    c.x = f2tf32(__uint_as_float(r.x));
    c.y = f2tf32(__uint_as_float(r.y));
    c.z = f2tf32(__uint_as_float(r.z));
    c.w = f2tf32(__uint_as_float(r.w));
    return c;
}
__device__ __forceinline__ void mma_tf32(float c[4],
                                         uint32_t a0, uint32_t a1, uint32_t a2, uint32_t a3,
                                         uint32_t b0, uint32_t b1){
    asm volatile(
        "mma.sync.aligned.m16n8k8.row.col.f32.tf32.tf32.f32 "
        "{%0,%1,%2,%3}, {%4,%5,%6,%7}, {%8,%9}, {%0,%1,%2,%3};"
        : "+f"(c[0]), "+f"(c[1]), "+f"(c[2]), "+f"(c[3])
        : "r"(a0), "r"(a1), "r"(a2), "r"(a3), "r"(b0), "r"(b1));
}

// ---------------- kernel ----------------
__global__ __launch_bounds__(THREADS, 1)
void expert_mlp_hmma2_kernel(const float* __restrict__ x, const float* __restrict__ cond,
                             const float* __restrict__ W1, const float* __restrict__ b1,
                             const float* __restrict__ W2, const float* __restrict__ b2,
                             float* __restrict__ out)
{
    extern __shared__ float sm[];
    float* s_xc = sm + OFF_XC;
    float* s_h  = sm + OFF_H;
    float* s_b1 = sm + OFF_B1;
    float* s_b2 = sm + OFF_B2;

    const int tid  = threadIdx.x;
    const int lane = tid & 31;
    const int wid  = tid >> 5;
    const int gr   = lane >> 2;
    const int ct   = lane & 3;
    const int mw   = wid & 3;       // warp M index (4)
    const int nw   = wid >> 2;      // warp N index (2)

    const int e  = blockIdx.x >> 5;           // 32 CTAs per expert
    const int m0 = (blockIdx.x & 31) * BM;

    const float* xp  = x    + (size_t)e * B_ * DX_ + (size_t)m0 * DX_;
    const float* cp_ = cond + (size_t)e * B_ * DC_ + (size_t)m0 * DC_;
    const float* w1p = W1   + (size_t)e * DH_ * DIN_;
    const float* w2p = W2   + (size_t)e * DO_ * DH_;
    float*       op  = out  + (size_t)e * B_ * DO_ + (size_t)m0 * DO_;

    // biases
    {
        const float4 v = *(const float4*)(b1 + (size_t)e * DH_ + tid * 4);
        *(float4*)(s_b1 + tid * 4) = v;
        if (tid < 32) {
            const float4 w = *(const float4*)(b2 + (size_t)e * DO_ + tid * 4);
            *(float4*)(s_b2 + tid * 4) = w;
        }
    }

    // ---- stage xc (once): permuted pairs, tf32. 128 rows x 24 groups = 3072 groups ----
    #pragma unroll
    for (int i = 0; i < 12; ++i) {
        const int gi = tid + i * THREADS;      // group index
        const int r  = gi / 24, g = gi % 24;
        float4 lo, hi;
        if (g < 16) {
            lo = *(const float4*)(xp + (size_t)r * DX_ + g * 8);
            hi = *(const float4*)(xp + (size_t)r * DX_ + g * 8 + 4);
        } else {
            lo = *(const float4*)(cp_ + (size_t)r * DC_ + (g - 16) * 8);
            hi = *(const float4*)(cp_ + (size_t)r * DC_ + (g - 16) * 8 + 4);
        }
        put_group(lo, hi, s_xc + r * SXC + g * 8);
    }

    // ---- stage chunk-0 weights (plain k-major, tf32) ----
    {
        const float* w1n = w1p;                       // chunk 0 rows
        #pragma unroll
        for (int i = 0; i < 6; ++i) {                 // 32 rows x 48 float4 = 1536
            const int idx = tid + i * THREADS;
            const int n = idx / 48, j = idx % 48;
            uint4 r = *(const uint4*)(w1n + (size_t)n * DIN_ + j * 4);
            *(uint4*)(sm + OFF_W1 + n * SW1 + j * 4) = cvt4(r);
        }
        #pragma unroll
        for (int i = 0; i < 4; ++i) {                 // 128 rows x 8 float4 = 1024
            const int idx = tid + i * THREADS;
            const int n = idx / 8, j = idx % 8;
            uint4 r = *(const uint4*)(w2p + (size_t)n * DH_ + j * 4);
            *(uint4*)(sm + OFF_W2 + n * SW2 + j * 4) = cvt4(r);
        }
    }
    __syncthreads();

    // y accumulators: warp tile 32 x 64
    float yacc[2][8][4];
    #pragma unroll
    for (int a = 0; a < 2; a++)
        #pragma unroll
        for (int b = 0; b < 8; b++)
            #pragma unroll
            for (int c = 0; c < 4; c++) yacc[a][b][c] = 0.0f;

    const int row0 = mw * 32 + gr;       // A row for tm=0 (tm=1 adds 16)

    for (int ch = 0; ch < NCH; ++ch) {
        const int buf = ch & 1;

        // ---- issue next chunk's weight LDGs (held in regs; stored at chunk end) ----
        uint4 r1[6], r2[4];
        if (ch + 1 < NCH) {
            const float* w1n = w1p + (size_t)(ch + 1) * CHN * DIN_;
            #pragma unroll
            for (int i = 0; i < 6; ++i) {
                const int idx = tid + i * THREADS;
                const int n = idx / 48, j = idx % 48;
                r1[i] = *(const uint4*)(w1n + (size_t)n * DIN_ + j * 4);
            }
            const float* w2n = w2p + (size_t)(ch + 1) * CHN;
            #pragma unroll
            for (int i = 0; i < 4; ++i) {
                const int idx = tid + i * THREADS;
                const int n = idx / 8, j = idx % 8;
                r2[i] = *(const uint4*)(w2n + (size_t)n * DH_ + j * 4);
            }
        }

        // ---- MMA1: h[128x32] = xc @ W1chunk^T ----
        const float* w1s = sm + OFF_W1 + buf * N_W1;
        float hacc[2][2][4];
        #pragma unroll
        for (int a = 0; a < 2; a++)
            #pragma unroll
            for (int b = 0; b < 2; b++)
                #pragma unroll
                for (int c = 0; c < 4; c++) hacc[a][b][c] = 0.0f;

        #pragma unroll
        for (int kt = 0; kt < DIN_ / 8; ++kt) {
            const int kp = kt * 8 + 2 * ct;          // permuted pair offset
            uint32_t A[2][4];
            #pragma unroll
            for (int tm = 0; tm < 2; ++tm) {
                const float2 u = *(const float2*)(s_xc + (row0 + tm * 16) * SXC + kp);
                const float2 v = *(const float2*)(s_xc + (row0 + tm * 16 + 8) * SXC + kp);
                A[tm][0] = __float_as_uint(u.x);
                A[tm][1] = __float_as_uint(v.x);
                A[tm][2] = __float_as_uint(u.y);
                A[tm][3] = __float_as_uint(v.y);
            }
            #pragma unroll
            for (int tn = 0; tn < 2; ++tn) {
                const int n = nw * 16 + tn * 8 + gr;
                const float* p = w1s + n * SW1 + kt * 8 + ct;
                const uint32_t b0 = __float_as_uint(p[0]);
                const uint32_t b1v = __float_as_uint(p[4]);
                #pragma unroll
                for (int tm = 0; tm < 2; ++tm)
                    mma_tf32(hacc[tm][tn], A[tm][0], A[tm][1], A[tm][2], A[tm][3], b0, b1v);
            }
        }

        // ---- epilogue: relu(h + b1) -> tf32, store permuted to s_h ----
        {
            const int w0 = 2 * ct, w1i = 2 * ct + 1;
            const int p0 = 2 * (w0 & 3) + ((w0 >> 2) & 1);
            const int p1 = 2 * (w1i & 3) + ((w1i >> 2) & 1);
            #pragma unroll
            for (int tn = 0; tn < 2; ++tn) {
                const int grp = nw * 16 + tn * 8;               // k-group base in h row
                const int n0  = grp + 2 * ct;                    // original column
                const float bb0 = s_b1[ch * CHN + n0];
                const float bb1 = s_b1[ch * CHN + n0 + 1];
                #pragma unroll
                for (int tm = 0; tm < 2; ++tm) {
                    const int row = row0 + tm * 16;
                    s_h[row * SH + grp + p0]       = tf32relu(hacc[tm][tn][0] + bb0);
                    s_h[row * SH + grp + p1]       = tf32relu(hacc[tm][tn][1] + bb1);
                    s_h[(row + 8) * SH + grp + p0] = tf32relu(hacc[tm][tn][2] + bb0);
                    s_h[(row + 8) * SH + grp + p1] = tf32relu(hacc[tm][tn][3] + bb1);
                }
            }
        }
        __syncthreads();   // h visible to all warps

        // ---- MMA2: y += h @ W2chunk^T ----
        const float* w2s = sm + OFF_W2 + buf * N_W2;
        #pragma unroll
        for (int kt = 0; kt < CHN / 8; ++kt) {
            const int kp = kt * 8 + 2 * ct;
            uint32_t A[2][4];
            #pragma unroll
            for (int tm = 0; tm < 2; ++tm) {
                const float2 u = *(const float2*)(s_h + (row0 + tm * 16) * SH + kp);
                const float2 v = *(const float2*)(s_h + (row0 + tm * 16 + 8) * SH + kp);
                A[tm][0] = __float_as_uint(u.x);
                A[tm][1] = __float_as_uint(v.x);
                A[tm][2] = __float_as_uint(u.y);
                A[tm][3] = __float_as_uint(v.y);
            }
            #pragma unroll
            for (int tn = 0; tn < 8; ++tn) {
                const int n = nw * 64 + tn * 8 + gr;
                const float* p = w2s + n * SW2 + kt * 8 + ct;
                const uint32_t b0 = __float_as_uint(p[0]);
                const uint32_t b1v = __float_as_uint(p[4]);
                #pragma unroll
                for (int tm = 0; tm < 2; ++tm)
                    mma_tf32(yacc[tm][tn], A[tm][0], A[tm][1], A[tm][2], A[tm][3], b0, b1v);
            }
        }

        // ---- store next chunk's weights (regs -> smem, tf32) ----
        if (ch + 1 < NCH) {
            float* d1 = sm + OFF_W1 + (buf ^ 1) * N_W1;
            #pragma unroll
            for (int i = 0; i < 6; ++i) {
                const int idx = tid + i * THREADS;
                const int n = idx / 48, j = idx % 48;
                *(uint4*)(d1 + n * SW1 + j * 4) = cvt4(r1[i]);
            }
            float* d2 = sm + OFF_W2 + (buf ^ 1) * N_W2;
            #pragma unroll
            for (int i = 0; i < 4; ++i) {
                const int idx = tid + i * THREADS;
                const int n = idx / 8, j = idx % 8;
                *(uint4*)(d2 + n * SW2 + j * 4) = cvt4(r2[i]);
            }
        }
        __syncthreads();   // next weights ready; h reads done before next epilogue
    }

    // ---- final epilogue: y + b2 -> gmem ----
    #pragma unroll
    for (int tn = 0; tn < 8; ++tn) {
        const int col = nw * 64 + tn * 8 + 2 * ct;
        const float bb0 = s_b2[col];
        const float bb1 = s_b2[col + 1];
        #pragma unroll
        for (int tm = 0; tm < 2; ++tm) {
            const int row = row0 + tm * 16;
            float2 lo, hi;
            lo.x = yacc[tm][tn][0] + bb0;
            lo.y = yacc[tm][tn][1] + bb1;
            hi.x = yacc[tm][tn][2] + bb0;
            hi.y = yacc[tm][tn][3] + bb1;
            *(float2*)(op + (size_t)row * DO_ + col)       = lo;
            *(float2*)(op + (size_t)(row + 8) * DO_ + col) = hi;
        }
    }
}

extern "C" void kernel_launch(void* const* d_in, const int* in_sizes, int n_in,
                              void* d_out, int out_size)
{
    const float* x    = (const float*)d_in[0];
    const float* cond = (const float*)d_in[1];
    const float* W1   = (const float*)d_in[2];
    const float* b1   = (const float*)d_in[3];
    const float* W2   = (const float*)d_in[4];
    const float* b2   = (const float*)d_in[5];
    float* out = (float*)d_out;

    cudaFuncSetAttribute(expert_mlp_hmma2_kernel,
                         cudaFuncAttributeMaxDynamicSharedMemorySize, SMEM_BYTES);

    const int grid = E_ * (B_ / BM);   // 512 CTAs
    expert_mlp_hmma2_kernel<<<grid, THREADS, SMEM_BYTES>>>(x, cond, W1, b1, W2, b2, out);
}

// round 5
// speedup vs baseline: 1.0845x; 1.0845x over previous
#include <cuda_runtime.h>
#include <cstdint>

// ---------------- problem constants ----------------
#define E_   16
#define B_   4096
#define DX_  128
#define DC_  64
#define DIN_ 192
#define DH_  1024
#define DO_  128

#define BM   128            // batch rows per CTA
#define CHN  32             // DH chunk
#define NCH  (DH_/CHN)      // 32 chunks
#define THREADS 256

// smem row strides (floats):
//  A-operand sources (64-bit pair loads): stride % 32 == 8
//  B-operand sources (32-bit loads):      stride % 32 == 4
#define SXC 200   // xc  [128][200]  permuted tf32 pairs
#define SW1 196   // W1  [32][196]   raw fp32 k-major, double buffered (cp.async)
#define SW2 36    // W2  [128][36]   raw fp32 k-major, double buffered (cp.async)
#define SH  40    // h   [128][40]   permuted tf32 pairs

// smem offsets in floats
#define OFF_XC 0
#define N_XC   (BM*SXC)                 // 25600
#define OFF_W1 (OFF_XC + N_XC)          // 25600
#define N_W1   (CHN*SW1)                // 6272 per buf
#define OFF_W2 (OFF_W1 + 2*N_W1)        // 38144
#define N_W2   (DO_*SW2)                // 4608 per buf
#define OFF_H  (OFF_W2 + 2*N_W2)        // 47360
#define N_H    (BM*SH)                  // 5120
#define OFF_B1 (OFF_H + N_H)            // 52480
#define OFF_B2 (OFF_B1 + DH_)           // 53504
#define SMEM_FLOATS (OFF_B2 + DO_)      // 53632
#define SMEM_BYTES  (SMEM_FLOATS*4)     // 214528

// ---------------- helpers ----------------
__device__ __forceinline__ uint32_t s2u(const void* p){
    uint32_t a;
    asm("{ .reg .u64 t; cvta.to.shared.u64 t, %1; cvt.u32.u64 %0, t; }" : "=r"(a) : "l"(p));
    return a;
}
__device__ __forceinline__ uint32_t f2tf32(float f){
    uint32_t u; asm("cvt.rna.tf32.f32 %0, %1;" : "=r"(u) : "f"(f)); return u;
}
__device__ __forceinline__ float tf32relu(float v){
    float r = fmaxf(v, 0.0f);
    uint32_t u; asm("cvt.rna.tf32.f32 %0, %1;" : "=r"(u) : "f"(r));
    return __uint_as_float(u);
}
// store one k-group of 8 (lo=k0..3, hi=k4..7) as pairs [0,4][1,5][2,6][3,7], tf32-converted
__device__ __forceinline__ void put_group(float4 lo, float4 hi, float* dst){
    uint2 p;
    p.x = f2tf32(lo.x); p.y = f2tf32(hi.x); *(uint2*)(dst + 0) = p;
    p.x = f2tf32(lo.y); p.y = f2tf32(hi.y); *(uint2*)(dst + 2) = p;
    p.x = f2tf32(lo.z); p.y = f2tf32(hi.z); *(uint2*)(dst + 4) = p;
    p.x = f2tf32(lo.w); p.y = f2tf32(hi.w); *(uint2*)(dst + 6) = p;
}
__device__ __forceinline__ void cp16(uint32_t dst, const void* src){
    asm volatile("cp.async.cg.shared.global [%0], [%1], 16;" :: "r"(dst), "l"(src) : "memory");
}
#define CP_COMMIT() asm volatile("cp.async.commit_group;" ::: "memory")
#define CP_WAIT0()  asm volatile("cp.async.wait_group 0;" ::: "memory")

__device__ __forceinline__ void mma_tf32(float c[4],
                                         uint32_t a0, uint32_t a1, uint32_t a2, uint32_t a3,
                                         uint32_t b0, uint32_t b1){
    asm volatile(
        "mma.sync.aligned.m16n8k8.row.col.f32.tf32.tf32.f32 "
        "{%0,%1,%2,%3}, {%4,%5,%6,%7}, {%8,%9}, {%0,%1,%2,%3};"
        : "+f"(c[0]), "+f"(c[1]), "+f"(c[2]), "+f"(c[3])
        : "r"(a0), "r"(a1), "r"(a2), "r"(a3), "r"(b0), "r"(b1));
}

// stage one DH chunk of W1 + W2 into smem buffer `buf` via cp.async (raw fp32)
__device__ __forceinline__ void stage_w(uint32_t sb, const float* __restrict__ w1p,
                                        const float* __restrict__ w2p, int ch, int buf, int tid)
{
    const float* w1src = w1p + (size_t)ch * CHN * DIN_;
    const uint32_t w1b = sb + (OFF_W1 + buf * N_W1) * 4;
    #pragma unroll
    for (int i = tid; i < CHN * 48; i += THREADS) {
        const int r = i / 48, j = i % 48;
        cp16(w1b + r * (SW1*4) + j * 16, w1src + r * DIN_ + j * 4);
    }
    const uint32_t w2b = sb + (OFF_W2 + buf * N_W2) * 4;
    #pragma unroll
    for (int i = tid; i < DO_ * 8; i += THREADS) {
        const int r = i / 8, j = i % 8;
        cp16(w2b + r * (SW2*4) + j * 16, w2p + (size_t)r * DH_ + ch * CHN + j * 4);
    }
}

// ---------------- kernel ----------------
__global__ __launch_bounds__(THREADS, 1)
void expert_mlp_hmma3_kernel(const float* __restrict__ x, const float* __restrict__ cond,
                             const float* __restrict__ W1, const float* __restrict__ b1,
                             const float* __restrict__ W2, const float* __restrict__ b2,
                             float* __restrict__ out)
{
    extern __shared__ float sm[];
    float* s_xc = sm + OFF_XC;
    float* s_h  = sm + OFF_H;
    float* s_b1 = sm + OFF_B1;
    float* s_b2 = sm + OFF_B2;
    const uint32_t sb = s2u(sm);

    const int tid  = threadIdx.x;
    const int lane = tid & 31;
    const int wid  = tid >> 5;
    const int gr   = lane >> 2;
    const int ct   = lane & 3;
    const int mw   = wid & 3;       // warp M index (4)
    const int nw   = wid >> 2;      // warp N index (2)

    const int e  = blockIdx.x >> 5;           // 32 CTAs per expert
    const int m0 = (blockIdx.x & 31) * BM;

    const float* xp  = x    + (size_t)e * B_ * DX_ + (size_t)m0 * DX_;
    const float* cp_ = cond + (size_t)e * B_ * DC_ + (size_t)m0 * DC_;
    const float* w1p = W1   + (size_t)e * DH_ * DIN_;
    const float* w2p = W2   + (size_t)e * DO_ * DH_;
    float*       op  = out  + (size_t)e * B_ * DO_ + (size_t)m0 * DO_;

    // stage chunk-0 weights first so cp.async overlaps the xc conversion work
    stage_w(sb, w1p, w2p, 0, 0, tid);
    CP_COMMIT();

    // biases
    {
        const float4 v = *(const float4*)(b1 + (size_t)e * DH_ + tid * 4);
        *(float4*)(s_b1 + tid * 4) = v;
        if (tid < 32) {
            const float4 w = *(const float4*)(b2 + (size_t)e * DO_ + tid * 4);
            *(float4*)(s_b2 + tid * 4) = w;
        }
    }

    // ---- stage xc (once): permuted tf32 pairs. 128 rows x 24 groups of 8 ----
    #pragma unroll
    for (int i = 0; i < 12; ++i) {
        const int gi = tid + i * THREADS;
        const int r  = gi / 24, g = gi % 24;
        float4 lo, hi;
        if (g < 16) {
            lo = *(const float4*)(xp + (size_t)r * DX_ + g * 8);
            hi = *(const float4*)(xp + (size_t)r * DX_ + g * 8 + 4);
        } else {
            lo = *(const float4*)(cp_ + (size_t)r * DC_ + (g - 16) * 8);
            hi = *(const float4*)(cp_ + (size_t)r * DC_ + (g - 16) * 8 + 4);
        }
        put_group(lo, hi, s_xc + r * SXC + g * 8);
    }
    CP_WAIT0();
    __syncthreads();

    // y accumulators: warp tile 32 x 64
    float yacc[2][8][4];
    #pragma unroll
    for (int a = 0; a < 2; a++)
        #pragma unroll
        for (int b = 0; b < 8; b++)
            #pragma unroll
            for (int c = 0; c < 4; c++) yacc[a][b][c] = 0.0f;

    const int row0 = mw * 32 + gr;       // A row for tm=0 (tm=1 adds 16)

    // h-store permutation: column w -> pair position 2*(w&3) + (w>>2)
    const int w0 = 2 * ct, w1i = 2 * ct + 1;
    const int p0 = 2 * (w0 & 3) + ((w0 >> 2) & 1);
    const int p1 = 2 * (w1i & 3) + ((w1i >> 2) & 1);

    for (int ch = 0; ch < NCH; ++ch) {
        const int buf = ch & 1;

        // prefetch next chunk's weights (cp.async, overlaps with compute)
        if (ch + 1 < NCH) stage_w(sb, w1p, w2p, ch + 1, buf ^ 1, tid);
        CP_COMMIT();

        // ---- MMA1: h[128x32] = xc @ W1chunk^T ----
        const float* w1s = sm + OFF_W1 + buf * N_W1;
        float hacc[2][2][4];
        #pragma unroll
        for (int a = 0; a < 2; a++)
            #pragma unroll
            for (int b = 0; b < 2; b++)
                #pragma unroll
                for (int c = 0; c < 4; c++) hacc[a][b][c] = 0.0f;

        #pragma unroll
        for (int kt = 0; kt < DIN_ / 8; ++kt) {
            const int kp = kt * 8 + 2 * ct;          // permuted pair offset
            uint32_t A[2][4];
            #pragma unroll
            for (int tm = 0; tm < 2; ++tm) {
                const float2 u = *(const float2*)(s_xc + (row0 + tm * 16) * SXC + kp);
                const float2 v = *(const float2*)(s_xc + (row0 + tm * 16 + 8) * SXC + kp);
                A[tm][0] = __float_as_uint(u.x);
                A[tm][1] = __float_as_uint(v.x);
                A[tm][2] = __float_as_uint(u.y);
                A[tm][3] = __float_as_uint(v.y);
            }
            #pragma unroll
            for (int tn = 0; tn < 2; ++tn) {
                const int n = nw * 16 + tn * 8 + gr;
                const float* p = w1s + n * SW1 + kt * 8 + ct;
                const uint32_t b0 = f2tf32(p[0]);
                const uint32_t b1v = f2tf32(p[4]);
                #pragma unroll
                for (int tm = 0; tm < 2; ++tm)
                    mma_tf32(hacc[tm][tn], A[tm][0], A[tm][1], A[tm][2], A[tm][3], b0, b1v);
            }
        }

        // ---- epilogue: relu(h + b1) -> tf32, store permuted to s_h ----
        #pragma unroll
        for (int tn = 0; tn < 2; ++tn) {
            const int grp = nw * 16 + tn * 8;               // k-group base in h row
            const int n0  = grp + 2 * ct;                    // original column
            const float bb0 = s_b1[ch * CHN + n0];
            const float bb1 = s_b1[ch * CHN + n0 + 1];
            #pragma unroll
            for (int tm = 0; tm < 2; ++tm) {
                const int row = row0 + tm * 16;
                s_h[row * SH + grp + p0]       = tf32relu(hacc[tm][tn][0] + bb0);
                s_h[row * SH + grp + p1]       = tf32relu(hacc[tm][tn][1] + bb1);
                s_h[(row + 8) * SH + grp + p0] = tf32relu(hacc[tm][tn][2] + bb0);
                s_h[(row + 8) * SH + grp + p1] = tf32relu(hacc[tm][tn][3] + bb1);
            }
        }
        __syncthreads();   // h visible to all warps

        // ---- MMA2: y += h @ W2chunk^T ----
        const float* w2s = sm + OFF_W2 + buf * N_W2;
        #pragma unroll
        for (int kt = 0; kt < CHN / 8; ++kt) {
            const int kp = kt * 8 + 2 * ct;
            uint32_t A[2][4];
            #pragma unroll
            for (int tm = 0; tm < 2; ++tm) {
                const float2 u = *(const float2*)(s_h + (row0 + tm * 16) * SH + kp);
                const float2 v = *(const float2*)(s_h + (row0 + tm * 16 + 8) * SH + kp);
                A[tm][0] = __float_as_uint(u.x);
                A[tm][1] = __float_as_uint(v.x);
                A[tm][2] = __float_as_uint(u.y);
                A[tm][3] = __float_as_uint(v.y);
            }
            #pragma unroll
            for (int tn = 0; tn < 8; ++tn) {
                const int n = nw * 64 + tn * 8 + gr;
                const float* p = w2s + n * SW2 + kt * 8 + ct;
                const uint32_t b0 = f2tf32(p[0]);
                const uint32_t b1v = f2tf32(p[4]);
                #pragma unroll
                for (int tm = 0; tm < 2; ++tm)
                    mma_tf32(yacc[tm][tn], A[tm][0], A[tm][1], A[tm][2], A[tm][3], b0, b1v);
            }
        }

        CP_WAIT0();        // next chunk's weights landed
        __syncthreads();   // h reads done before next epilogue overwrites s_h
    }

    // ---- final epilogue: y + b2 -> gmem ----
    #pragma unroll
    for (int tn = 0; tn < 8; ++tn) {
        const int col = nw * 64 + tn * 8 + 2 * ct;
        const float bb0 = s_b2[col];
        const float bb1 = s_b2[col + 1];
        #pragma unroll
        for (int tm = 0; tm < 2; ++tm) {
            const int row = row0 + tm * 16;
            float2 lo, hi;
            lo.x = yacc[tm][tn][0] + bb0;
            lo.y = yacc[tm][tn][1] + bb1;
            hi.x = yacc[tm][tn][2] + bb0;
            hi.y = yacc[tm][tn][3] + bb1;
            *(float2*)(op + (size_t)row * DO_ + col)       = lo;
            *(float2*)(op + (size_t)(row + 8) * DO_ + col) = hi;
        }
    }
}

extern "C" void kernel_launch(void* const* d_in, const int* in_sizes, int n_in,
                              void* d_out, int out_size)
{
    const float* x    = (const float*)d_in[0];
    const float* cond = (const float*)d_in[1];
    const float* W1   = (const float*)d_in[2];
    const float* b1   = (const float*)d_in[3];
    const float* W2   = (const float*)d_in[4];
    const float* b2   = (const float*)d_in[5];
    float* out = (float*)d_out;

    cudaFuncSetAttribute(expert_mlp_hmma3_kernel,
                         cudaFuncAttributeMaxDynamicSharedMemorySize, SMEM_BYTES);

    const int grid = E_ * (B_ / BM);   // 512 CTAs
    expert_mlp_hmma3_kernel<<<grid, THREADS, SMEM_BYTES>>>(x, cond, W1, b1, W2, b2, out);
}

// round 6
// speedup vs baseline: 1.3246x; 1.2214x over previous
#include <cuda_runtime.h>
#include <cstdint>

// ---------------- problem constants ----------------
#define E_   16
#define B_   4096
#define DX_  128
#define DC_  64
#define DIN_ 192
#define DH_  1024
#define DO_  128

#define BM   128            // batch rows per CTA
#define CHN  32             // DH chunk
#define NCH  (DH_/CHN)      // 32 chunks
#define THREADS 256

// pair/row permutation within 8-groups: l -> ((l&3)<<1) | (l>>2)
#define PERM(l) ((((l)&3)<<1) | ((l)>>2))

// smem strides (floats), stride % 32 == 8 -> conflict-free LDS.64 fragment loads
#define SXC 200   // xc  [128][200]  pair-permuted tf32
#define SW1 200   // W1  [32][200]   prepacked tf32 (n sigma-permuted, k pair-permuted), x2 buf
#define SW2 40    // W2  [128][40]   prepacked tf32 (k pair-permuted), x2 buf

#define OFF_XC 0
#define N_XC   (BM*SXC)                  // 25600
#define OFF_W1 (OFF_XC + N_XC)           // 25600
#define N_W1B  (CHN*SW1)                 // 6400 per buf
#define OFF_W2 (OFF_W1 + 2*N_W1B)        // 38400
#define N_W2B  (DO_*SW2)                 // 5120 per buf
#define OFF_B1 (OFF_W2 + 2*N_W2B)        // 48640
#define OFF_B2 (OFF_B1 + DH_)            // 49664
#define SMEM_FLOATS (OFF_B2 + DO_)       // 49792
#define SMEM_BYTES  (SMEM_FLOATS*4)      // 199168

// ---------------- prepacked weight scratch (device globals: allowed) ----------------
__device__ float g_w1p[(size_t)E_ * DH_ * DIN_];   // 12.6 MB
__device__ float g_w2p[(size_t)E_ * DO_ * DH_];    //  8.4 MB
__device__ float g_b1p[E_ * DH_];

#define N1 (E_*DH_*DIN_)    // 3145728
#define N2 (E_*DO_*DH_)     // 2097152
#define N3 (E_*DH_)         // 16384
#define NPRE (N1 + N2 + N3) // 5259264 = 20544 * 256

// ---------------- helpers ----------------
__device__ __forceinline__ uint32_t s2u(const void* p){
    uint32_t a;
    asm("{ .reg .u64 t; cvta.to.shared.u64 t, %1; cvt.u32.u64 %0, t; }" : "=r"(a) : "l"(p));
    return a;
}
__device__ __forceinline__ uint32_t f2tf32(float f){
    uint32_t u; asm("cvt.rna.tf32.f32 %0, %1;" : "=r"(u) : "f"(f)); return u;
}
__device__ __forceinline__ float tf32f(float f){
    return __uint_as_float(f2tf32(f));
}
__device__ __forceinline__ uint32_t tf32relu_u(float v){
    return f2tf32(fmaxf(v, 0.0f));
}
// store one k-group of 8 (lo=k0..3, hi=k4..7) as pairs [0,4][1,5][2,6][3,7], tf32
__device__ __forceinline__ void put_group(float4 lo, float4 hi, float* dst){
    uint2 p;
    p.x = f2tf32(lo.x); p.y = f2tf32(hi.x); *(uint2*)(dst + 0) = p;
    p.x = f2tf32(lo.y); p.y = f2tf32(hi.y); *(uint2*)(dst + 2) = p;
    p.x = f2tf32(lo.z); p.y = f2tf32(hi.z); *(uint2*)(dst + 4) = p;
    p.x = f2tf32(lo.w); p.y = f2tf32(hi.w); *(uint2*)(dst + 6) = p;
}
__device__ __forceinline__ void cp16(uint32_t dst, const void* src){
    asm volatile("cp.async.cg.shared.global [%0], [%1], 16;" :: "r"(dst), "l"(src) : "memory");
}
#define CP_COMMIT() asm volatile("cp.async.commit_group;" ::: "memory")
#define CP_WAIT0()  asm volatile("cp.async.wait_group 0;" ::: "memory")
#define CP_WAIT1()  asm volatile("cp.async.wait_group 1;" ::: "memory")

__device__ __forceinline__ void mma_tf32(float c[4],
                                         uint32_t a0, uint32_t a1, uint32_t a2, uint32_t a3,
                                         uint32_t b0, uint32_t b1){
    asm volatile(
        "mma.sync.aligned.m16n8k8.row.col.f32.tf32.tf32.f32 "
        "{%0,%1,%2,%3}, {%4,%5,%6,%7}, {%8,%9}, {%0,%1,%2,%3};"
        : "+f"(c[0]), "+f"(c[1]), "+f"(c[2]), "+f"(c[3])
        : "r"(a0), "r"(a1), "r"(a2), "r"(a3), "r"(b0), "r"(b1));
}

// ---------------- prepack: W1/W2 -> tf32 + permutations, b1 -> permuted ----------------
__global__ __launch_bounds__(256)
void prepack_kernel(const float* __restrict__ W1, const float* __restrict__ b1,
                    const float* __restrict__ W2)
{
    const int i = blockIdx.x * 256 + threadIdx.x;
    if (i < N1) {
        const int k = i % DIN_;
        const int n = (i / DIN_) % DH_;
        const int e = i / (DIN_ * DH_);
        const int kp = (k & ~7) | PERM(k & 7);
        const int np = (n & ~7) | PERM(n & 7);   // sigma-permute rows: D cols land frag-ready
        g_w1p[((size_t)e * DH_ + np) * DIN_ + kp] = tf32f(W1[i]);
    } else if (i < N1 + N2) {
        const int j = i - N1;
        const int k = j % DH_;
        const int n = (j / DH_) % DO_;
        const int e = j / (DH_ * DO_);
        const int kp = (k & ~7) | PERM(k & 7);
        g_w2p[((size_t)e * DO_ + n) * DH_ + kp] = tf32f(W2[j]);
    } else if (i < NPRE) {
        const int j = i - N1 - N2;
        const int k = j % DH_;
        const int e = j / DH_;
        const int kp = (k & ~7) | PERM(k & 7);
        g_b1p[e * DH_ + kp] = b1[j];             // raw f32 value, permuted position
    }
}

// stage one DH chunk of prepacked W1 + W2 into smem buffer via cp.async
__device__ __forceinline__ void stage_w(uint32_t sb, const float* __restrict__ w1p,
                                        const float* __restrict__ w2p, int ch, int buf, int tid)
{
    const float* src1 = w1p + (size_t)ch * CHN * DIN_;
    const uint32_t d1 = sb + (OFF_W1 + buf * N_W1B) * 4;
    #pragma unroll
    for (int i = 0; i < 6; ++i) {                 // 32 rows x 48 cp16
        const int idx = tid + i * THREADS;
        const int r = idx / 48, j = idx % 48;
        cp16(d1 + r * (SW1*4) + j * 16, src1 + r * DIN_ + j * 4);
    }
    const float* src2 = w2p + (size_t)ch * CHN;   // k-window (8-group aligned)
    const uint32_t d2 = sb + (OFF_W2 + buf * N_W2B) * 4;
    #pragma unroll
    for (int i = 0; i < 4; ++i) {                 // 128 rows x 8 cp16
        const int idx = tid + i * THREADS;
        const int r = idx / 8, j = idx % 8;
        cp16(d2 + r * (SW2*4) + j * 16, src2 + (size_t)r * DH_ + j * 4);
    }
}

// ---------------- main kernel ----------------
__global__ __launch_bounds__(THREADS, 1)
void expert_mlp_regh_kernel(const float* __restrict__ x, const float* __restrict__ cond,
                            const float* __restrict__ b2, float* __restrict__ out)
{
    extern __shared__ float sm[];
    float* s_xc = sm + OFF_XC;
    float* s_b1 = sm + OFF_B1;
    float* s_b2 = sm + OFF_B2;
    const uint32_t sb = s2u(sm);

    const int tid  = threadIdx.x;
    const int lane = tid & 31;
    const int wid  = tid >> 5;
    const int gr   = lane >> 2;
    const int ct   = lane & 3;

    const int e  = blockIdx.x >> 5;           // 32 CTAs per expert
    const int m0 = (blockIdx.x & 31) * BM;

    const float* xp  = x    + (size_t)e * B_ * DX_ + (size_t)m0 * DX_;
    const float* cp_ = cond + (size_t)e * B_ * DC_ + (size_t)m0 * DC_;
    const float* w1p = g_w1p + (size_t)e * DH_ * DIN_;
    const float* w2p = g_w2p + (size_t)e * DO_ * DH_;
    float*       op  = out  + (size_t)e * B_ * DO_ + (size_t)m0 * DO_;

    // stage chunk-0 weights first (overlaps with xc conversion below)
    stage_w(sb, w1p, w2p, 0, 0, tid);
    CP_COMMIT();

    // biases: full permuted b1 (f32), b2
    {
        const float4 v = *(const float4*)(g_b1p + e * DH_ + tid * 4);
        *(float4*)(s_b1 + tid * 4) = v;
        if (tid < 32) {
            const float4 w = *(const float4*)(b2 + (size_t)e * DO_ + tid * 4);
            *(float4*)(s_b2 + tid * 4) = w;
        }
    }

    // stage xc: pair-permuted tf32. 128 rows x 24 groups of 8
    #pragma unroll
    for (int i = 0; i < 12; ++i) {
        const int gi = tid + i * THREADS;
        const int r  = gi / 24, g = gi % 24;
        float4 lo, hi;
        if (g < 16) {
            lo = *(const float4*)(xp + (size_t)r * DX_ + g * 8);
            hi = *(const float4*)(xp + (size_t)r * DX_ + g * 8 + 4);
        } else {
            lo = *(const float4*)(cp_ + (size_t)r * DC_ + (g - 16) * 8);
            hi = *(const float4*)(cp_ + (size_t)r * DC_ + (g - 16) * 8 + 4);
        }
        put_group(lo, hi, s_xc + r * SXC + g * 8);
    }
    __syncthreads();

    // y accumulators: warp owns 16 rows x 128 cols -> 16 n-tiles x 4 regs
    float yacc[16][4];
    #pragma unroll
    for (int t = 0; t < 16; ++t)
        #pragma unroll
        for (int c = 0; c < 4; ++c) yacc[t][c] = 0.0f;

    const int arow = wid * 16 + gr;     // this thread's lower A row
    const int kpo  = 2 * ct;            // pair offset within k-group

    for (int ch = 0; ch < NCH; ++ch) {
        const int buf = ch & 1;

        __syncthreads();                 // all warps done reading buf^1 (chunk ch-1)
        if (ch + 1 < NCH) {
            stage_w(sb, w1p, w2p, ch + 1, buf ^ 1, tid);
            CP_COMMIT();
            CP_WAIT1();                  // current buf's group complete
        } else {
            CP_WAIT0();
        }

        const float* w1s = sm + OFF_W1 + buf * N_W1B;
        const float* w2s = sm + OFF_W2 + buf * N_W2B;

        // ---- MMA1: h[16x32] = xc(warp rows) @ W1chunk^T (all in this warp) ----
        float hacc[4][4];
        #pragma unroll
        for (int t = 0; t < 4; ++t)
            #pragma unroll
            for (int c = 0; c < 4; ++c) hacc[t][c] = 0.0f;

        #pragma unroll
        for (int kt = 0; kt < DIN_ / 8; ++kt) {
            const int kp = kt * 8 + kpo;
            const float2 u = *(const float2*)(s_xc + arow * SXC + kp);
            const float2 v = *(const float2*)(s_xc + (arow + 8) * SXC + kp);
            const uint32_t a0 = __float_as_uint(u.x);
            const uint32_t a1 = __float_as_uint(v.x);
            const uint32_t a2 = __float_as_uint(u.y);
            const uint32_t a3 = __float_as_uint(v.y);
            #pragma unroll
            for (int tn = 0; tn < 4; ++tn) {
                const float2 b = *(const float2*)(w1s + (tn * 8 + gr) * SW1 + kp);
                mma_tf32(hacc[tn], a0, a1, a2, a3,
                         __float_as_uint(b.x), __float_as_uint(b.y));
            }
        }

        // ---- register epilogue: relu(h + b1) -> tf32, reorder D->A (free) ----
        uint32_t ah[4][4];
        const float* b1s = s_b1 + ch * CHN;
        #pragma unroll
        for (int t = 0; t < 4; ++t) {
            const float2 bb = *(const float2*)(b1s + t * 8 + kpo);  // (b[ct], b[ct+4])
            ah[t][0] = tf32relu_u(hacc[t][0] + bb.x);   // a0 = d0 (row gr,  k ct)
            ah[t][2] = tf32relu_u(hacc[t][1] + bb.y);   // a2 = d1 (row gr,  k ct+4)
            ah[t][1] = tf32relu_u(hacc[t][2] + bb.x);   // a1 = d2 (row gr+8,k ct)
            ah[t][3] = tf32relu_u(hacc[t][3] + bb.y);   // a3 = d3 (row gr+8,k ct+4)
        }

        // ---- MMA2: y[16x128] += h(frags in regs) @ W2chunk^T ----
        #pragma unroll
        for (int t = 0; t < 4; ++t) {
            const int kb = t * 8 + kpo;
            #pragma unroll
            for (int tn = 0; tn < 16; ++tn) {
                const float2 b = *(const float2*)(w2s + (tn * 8 + gr) * SW2 + kb);
                mma_tf32(yacc[tn], ah[t][0], ah[t][1], ah[t][2], ah[t][3],
                         __float_as_uint(b.x), __float_as_uint(b.y));
            }
        }
    }

    // ---- final epilogue: y + b2 -> gmem ----
    #pragma unroll
    for (int tn = 0; tn < 16; ++tn) {
        const int col = tn * 8 + 2 * ct;
        const float2 bb = *(const float2*)(s_b2 + col);
        float2 lo, hi;
        lo.x = yacc[tn][0] + bb.x;
        lo.y = yacc[tn][1] + bb.y;
        hi.x = yacc[tn][2] + bb.x;
        hi.y = yacc[tn][3] + bb.y;
        *(float2*)(op + (size_t)arow * DO_ + col)       = lo;
        *(float2*)(op + (size_t)(arow + 8) * DO_ + col) = hi;
    }
}

extern "C" void kernel_launch(void* const* d_in, const int* in_sizes, int n_in,
                              void* d_out, int out_size)
{
    const float* x    = (const float*)d_in[0];
    const float* cond = (const float*)d_in[1];
    const float* W1   = (const float*)d_in[2];
    const float* b1   = (const float*)d_in[3];
    const float* W2   = (const float*)d_in[4];
    const float* b2   = (const float*)d_in[5];
    float* out = (float*)d_out;

    prepack_kernel<<<NPRE / 256, 256>>>(W1, b1, W2);

    cudaFuncSetAttribute(expert_mlp_regh_kernel,
                         cudaFuncAttributeMaxDynamicSharedMemorySize, SMEM_BYTES);
    const int grid = E_ * (B_ / BM);   // 512 CTAs
    expert_mlp_regh_kernel<<<grid, THREADS, SMEM_BYTES>>>(x, cond, b2, out);
}